// round 4
// baseline (speedup 1.0000x reference)
#include <cuda_runtime.h>
#include <math.h>

#define BB 4
#define TT 2048
#define CC 48
#define DD 512
#define LL 16
#define KK 9
#define CSZ 15
#define NTR 15
#define NCAND 45
#define WINLEN 19
#define TP8 (TT + 8)

// ------------------- device scratch (static, no allocs) -------------------
__device__ float g_prob[BB * TT * CC];
__device__ float g_lse[BB * TT];
__device__ float g_ent2[BB * TT];
__device__ float g_cross[BB * 8 * TP8];   // d = 1..8 (d=0 analytic)
__device__ int   g_bdy[BB * NTR];
__device__ float g_fr_part[BB];
__device__ float g_glc_part[BB * LL];

// order-preserving float -> uint32 (suppressed marker 0 is minimal)
__device__ __forceinline__ unsigned f2sortable(float f) {
    unsigned u = __float_as_uint(f);
    return (u & 0x80000000u) ? ~u : (u | 0x80000000u);
}

// pack a float literal into both halves of an f32x2 register
__device__ __forceinline__ unsigned long long pk2f(float c) {
    unsigned long long r;
    asm("mov.b64 %0, {%1,%1};" : "=l"(r) : "f"(c));
    return r;
}

// Cephes log2 on two values via packed f32x2 FMA pipe
__device__ __forceinline__ float2 fast_log2_x2(float x0, float x1) {
    unsigned u0 = __float_as_uint(x0), u1 = __float_as_uint(x1);
    int e0 = (int)(u0 >> 23) - 127, e1 = (int)(u1 >> 23) - 127;
    float m0 = __uint_as_float((u0 & 0x007fffffu) | 0x3f800000u);
    float m1 = __uint_as_float((u1 & 0x007fffffu) | 0x3f800000u);
    if (m0 > 1.4142135f) { m0 *= 0.5f; e0 += 1; }
    if (m1 > 1.4142135f) { m1 *= 0.5f; e1 += 1; }
    float z0 = m0 - 1.f, z1 = m1 - 1.f;
    unsigned long long Z, Z2, P, W, Y, E, R;
    asm("mov.b64 %0, {%1,%2};" : "=l"(Z) : "f"(z0), "f"(z1));
    asm("mul.rn.f32x2 %0, %1, %1;" : "=l"(Z2) : "l"(Z));
    P = pk2f(7.0376836292e-2f);
    asm("fma.rn.f32x2 %0, %1, %2, %3;" : "=l"(P) : "l"(P), "l"(Z), "l"(pk2f(-1.1514610310e-1f)));
    asm("fma.rn.f32x2 %0, %1, %2, %3;" : "=l"(P) : "l"(P), "l"(Z), "l"(pk2f( 1.1676998740e-1f)));
    asm("fma.rn.f32x2 %0, %1, %2, %3;" : "=l"(P) : "l"(P), "l"(Z), "l"(pk2f(-1.2420140846e-1f)));
    asm("fma.rn.f32x2 %0, %1, %2, %3;" : "=l"(P) : "l"(P), "l"(Z), "l"(pk2f( 1.4249322787e-1f)));
    asm("fma.rn.f32x2 %0, %1, %2, %3;" : "=l"(P) : "l"(P), "l"(Z), "l"(pk2f(-1.6668057665e-1f)));
    asm("fma.rn.f32x2 %0, %1, %2, %3;" : "=l"(P) : "l"(P), "l"(Z), "l"(pk2f( 2.0000714765e-1f)));
    asm("fma.rn.f32x2 %0, %1, %2, %3;" : "=l"(P) : "l"(P), "l"(Z), "l"(pk2f(-2.4999993993e-1f)));
    asm("fma.rn.f32x2 %0, %1, %2, %3;" : "=l"(P) : "l"(P), "l"(Z), "l"(pk2f( 3.3333331174e-1f)));
    asm("fma.rn.f32x2 %0, %1, %2, %3;" : "=l"(W) : "l"(Z2), "l"(pk2f(-0.5f)), "l"(Z));
    asm("mul.rn.f32x2 %0, %1, %2;" : "=l"(P) : "l"(P), "l"(Z));
    asm("fma.rn.f32x2 %0, %1, %2, %3;" : "=l"(Y) : "l"(P), "l"(Z2), "l"(W));
    float ef0 = (float)e0, ef1 = (float)e1;
    asm("mov.b64 %0, {%1,%2};" : "=l"(E) : "f"(ef0), "f"(ef1));
    asm("fma.rn.f32x2 %0, %1, %2, %3;" : "=l"(R) : "l"(Y), "l"(pk2f(1.44269504089f)), "l"(E));
    float r0, r1;
    asm("mov.b64 {%0,%1}, %2;" : "=f"(r0), "=f"(r1) : "l"(R));
    return make_float2(r0, r1);
}

// ------------------- K1: softmax rows + lse + ent2 ------------------------
__global__ void k1_softmax(const float* __restrict__ fr) {
    int gw = (blockIdx.x * blockDim.x + threadIdx.x) >> 5;
    int lane = threadIdx.x & 31;
    if (gw >= BB * TT) return;
    const float* row = fr + (size_t)gw * CC;
    float x0 = row[lane];
    float x1 = (lane < 16) ? row[lane + 32] : -INFINITY;
    float m = fmaxf(x0, x1);
    #pragma unroll
    for (int o = 16; o > 0; o >>= 1) m = fmaxf(m, __shfl_xor_sync(0xffffffffu, m, o));
    float e0 = __expf(x0 - m);
    float e1 = (lane < 16) ? __expf(x1 - m) : 0.f;
    float s = e0 + e1;
    #pragma unroll
    for (int o = 16; o > 0; o >>= 1) s += __shfl_xor_sync(0xffffffffu, s, o);
    float inv = 1.f / s;
    float p0 = e0 * inv, p1 = e1 * inv;
    float ent = (p0 > 0.f) ? p0 * __log2f(p0) : 0.f;
    if (lane < 16) ent += (p1 > 0.f) ? p1 * __log2f(p1) : 0.f;
    #pragma unroll
    for (int o = 16; o > 0; o >>= 1) ent += __shfl_xor_sync(0xffffffffu, ent, o);
    float* pr = g_prob + (size_t)gw * CC;
    pr[lane] = p0;
    if (lane < 16) pr[lane + 32] = p1;
    if (lane == 0) {
        g_lse[gw] = m + __logf(s);
        g_ent2[gw] = ent;
    }
}

// ------------------- K2: crossD[d][rmin], d = 1..8, dual-pipe log ----------
__global__ void k2_cross() {
    int gw = (blockIdx.x * blockDim.x + threadIdx.x) >> 5;
    int lane = threadIdx.x & 31;
    const int ntask = BB * 8 * TP8;
    if (gw >= ntask) return;
    int b = gw / (8 * TP8);
    int rem = gw % (8 * TP8);
    int d = rem / TP8 + 1;   // 1..8 (warp-uniform)
    int r4 = rem % TP8;
    int r1 = r4 - 4;
    int r2 = r1 + d;
    const float2* base = (const float2*)(g_prob + (size_t)b * TT * CC);
    float acc = 0.f;
    if (lane < 24) {
        float2 a = (r1 >= 0 && r1 < TT) ? base[r1 * 24 + lane] : make_float2(0.f, 0.f);
        float2 c = (r2 >= 0 && r2 < TT) ? base[r2 * 24 + lane] : make_float2(0.f, 0.f);
        float sv0 = a.x + c.x, sv1 = a.y + c.y;
        float x0 = 0.5f * sv0 + 1e-32f;
        float x1 = 0.5f * sv1 + 1e-32f;
        float lg0, lg1;
        if (d <= 3) {              // FMA-pipe poly warps
            float2 lg = fast_log2_x2(x0, x1);
            lg0 = lg.x; lg1 = lg.y;
        } else {                   // MUFU warps
            lg0 = __log2f(x0);
            lg1 = __log2f(x1);
        }
        acc = sv0 * lg0 + sv1 * lg1;
    }
    #pragma unroll
    for (int o = 16; o > 0; o >>= 1) acc += __shfl_xor_sync(0xffffffffu, acc, o);
    if (lane == 0) g_cross[(b * 8 + (d - 1)) * TP8 + r4] = acc;
}

// ------------------- K4: score + detect + CE, per batch --------------------
__global__ void k4_detect(const float* __restrict__ fr_logit,
                          const int* __restrict__ transcript) {
    __shared__ __align__(16) unsigned ss[TT];   // sortable scores (0 = suppressed)
    __shared__ float sfs[TT];                   // float scores
    __shared__ float sent[TT];
    __shared__ int scand[NCAND];
    __shared__ int scand2[NCAND];
    __shared__ int s_tr[LL];
    __shared__ float scls[NTR * NCAND];
    __shared__ signed char sdir[NCAND * 31];
    __shared__ int sbdy[NTR];
    __shared__ float sred[8];

    int b = blockIdx.x;
    int tid = threadIdx.x;
    int lane = tid & 31;
    int wrp = tid >> 5;

    // ---- phase A: compute boundary scores in-block (old k3) ----------------
    for (int t = tid; t < TT; t += 256) sent[t] = g_ent2[b * TT + t];
    if (tid < LL) s_tr[tid] = transcript[b * LL + tid];
    __syncthreads();
    for (int t = tid; t < TT; t += 256) {
        float se = 0.f;
        #pragma unroll
        for (int i = 0; i < 4; i++) {
            int r = t - 4 + i;
            se += (r >= 0) ? sent[r] : 0.f;
        }
        float cs = 0.f;
        #pragma unroll
        for (int d = 1; d <= 8; d++) {
            const float* crb = g_cross + (size_t)(b * 8 + d - 1) * TP8 + t;
            #pragma unroll
            for (int i = 0; i + d <= 8; i++) {
                float w = ((i < 4) == ((i + d) < 4)) ? 2.f : -2.f;
                cs += w * crb[i];
            }
        }
        float sc = (4.f * se + cs) * (1.f / 81.f);
        if (t == 0) sc = -INFINITY;
        sfs[t] = sc;
        ss[t] = f2sortable(sc);
    }
    __syncthreads();

    // ---- warp 0: 45 incremental argmax iterations --------------------------
    if (tid < 32) {
        const uint4* s4c = (const uint4*)ss;
        unsigned v0 = 0u, v1 = 0u;
        #pragma unroll
        for (int q = 0; q < 8; q++) {
            uint4 a = s4c[lane * 8 + q];
            uint4 c = s4c[(lane + 32) * 8 + q];
            v0 = max(v0, max(max(a.x, a.y), max(a.z, a.w)));
            v1 = max(v1, max(max(c.x, c.y), max(c.z, c.w)));
        }
        for (int it = 0; it < NCAND; it++) {
            unsigned loc = max(v0, v1);
            unsigned mv = __reduce_max_sync(0xffffffffu, loc);
            unsigned m0 = __ballot_sync(0xffffffffu, v0 == mv);
            unsigned m1 = __ballot_sync(0xffffffffu, v1 == mv);
            int seg = m0 ? (__ffs(m0) - 1) : (32 + __ffs(m1) - 1);
            unsigned val = ss[seg * 32 + lane];
            unsigned mask = __ballot_sync(0xffffffffu, val == mv);
            int pick = seg * 32 + (__ffs(mask) - 1);
            if (lane == 0) scand[it] = pick;
            __syncwarp();
            // suppression + rescan fused: <=3 lanes, uint4 granularity
            int lo = pick - WINLEN, hi = pick + WINLEN;
            int slo = (lo < 0 ? 0 : lo) >> 5;
            int shi = ((hi > TT - 1 ? TT - 1 : hi)) >> 5;
            int nseg = shi - slo + 1;
            unsigned nv = 0u;
            if (lane < nseg) {
                int s = slo + lane;
                uint4* s4 = (uint4*)(ss + s * 32);
                int base = s * 32;
                #pragma unroll
                for (int q = 0; q < 8; q++) {
                    uint4 v = s4[q];
                    int idx = base + q * 4;
                    v.x = (idx     >= lo && idx     <= hi) ? 0u : v.x;
                    v.y = (idx + 1 >= lo && idx + 1 <= hi) ? 0u : v.y;
                    v.z = (idx + 2 >= lo && idx + 2 <= hi) ? 0u : v.z;
                    v.w = (idx + 3 >= lo && idx + 3 <= hi) ? 0u : v.w;
                    s4[q] = v;
                    nv = max(nv, max(max(v.x, v.y), max(v.z, v.w)));
                }
            }
            #pragma unroll
            for (int k2 = 0; k2 < 3; k2++) {
                unsigned m = __shfl_sync(0xffffffffu, nv, k2);
                int sg = slo + k2;
                if (k2 < nseg) {
                    if (sg == lane) v0 = m;
                    if (sg == lane + 32) v1 = m;
                }
            }
            __syncwarp();
        }
        // parallel rank sort (distinct indices -> unique ranks)
        int c0 = scand[lane];
        int c1 = (lane + 32 < NCAND) ? scand[lane + 32] : 0x7fffffff;
        int r0 = 0, r1 = 0;
        for (int j = 0; j < NCAND; j++) {
            int cj = scand[j];
            r0 += (cj < c0);
            r1 += (cj < c1);
        }
        scand2[r0] = c0;
        if (lane + 32 < NCAND) scand2[r1] = c1;
    }
    __syncthreads();

    // ---- cls matrix --------------------------------------------------------
    const float* pb = g_prob + (size_t)b * TT * CC;
    for (int e = tid; e < NTR * NCAND; e += 256) {
        int tr_i = e / NCAND;
        int n = e % NCAND;
        int cn = scand2[n];
        int ca = s_tr[tr_i], cb = s_tr[tr_i + 1];
        float sacc = 0.f;
        #pragma unroll
        for (int sft = 0; sft < CSZ; sft++) {
            int r = cn + sft - 7;
            if (r >= 0 && r < TT) {
                float sign = (sft < 7) ? 1.f : -1.f;
                sacc += sign * (pb[r * CC + ca] - pb[r * CC + cb]);
            }
        }
        scls[e] = sacc * (1.f / 30.f) + sfs[cn];
    }
    __syncthreads();

    // ---- DP: 31 lanes, one column each; backtrace on lane 0 ----------------
    if (tid < 32) {
        int j = lane;
        const float FINF = INFINITY;
        bool active = (j < 31);
        float prev;
        if (j == 0) prev = 0.f;
        else if (j == 1) prev = -scls[0 * NCAND + 0];
        else prev = FINF;
        if (active) sdir[j] = (j == 1) ? 1 : 0;
        int ta = j >> 1; if (ta > NTR - 1) ta = NTR - 1;
        bool even = ((j & 1) == 0);
        for (int ii = 1; ii < NCAND; ii++) {
            float dm1 = __shfl_up_sync(0xffffffffu, prev, 1);
            float dm2 = __shfl_up_sync(0xffffffffu, prev, 2);
            if (j < 1) dm1 = FINF;
            if (j < 2) dm2 = FINF;
            float nv; signed char nd;
            if (j >= 2) {
                if (even) {
                    nv = fminf(prev, dm1);
                    nd = (prev < dm1) ? 0 : 1;
                } else {
                    nv = -scls[ta * NCAND + ii] + fminf(dm1, dm2);
                    nd = (dm1 < dm2) ? 1 : 2;
                }
            } else if (j == 0) {
                nv = (ii < NCAND - NTR) ? 0.f : FINF; nd = 0;
            } else {
                bool ok = (ii <= NCAND - NTR);
                nv = ok ? -scls[0 * NCAND + ii] : FINF;
                nd = ok ? 1 : 0;
            }
            prev = nv;
            if (active) sdir[ii * 31 + j] = nd;
        }
        float p30 = __shfl_sync(0xffffffffu, prev, 30);
        float p29 = __shfl_sync(0xffffffffu, prev, 29);
        if (j == 0) {
            int cj = (p30 < p29) ? 30 : 29;
            int outi[NCAND];
            #pragma unroll
            for (int ii = NCAND - 1; ii >= 0; ii--) {
                outi[ii] = (cj & 1) ? (cj >> 1) : NTR;
                cj -= sdir[ii * 31 + cj];
            }
            int res[NTR];
            #pragma unroll
            for (int k2 = 0; k2 < NTR; k2++) res[k2] = 0;
            #pragma unroll
            for (int ii = 0; ii < NCAND; ii++) {
                int oi = outi[ii];
                if (oi < NTR) res[oi] = ii;
            }
            #pragma unroll
            for (int k2 = 0; k2 < NTR; k2++) {
                int bv = scand2[res[k2]];
                sbdy[k2] = bv;
                g_bdy[b * NTR + k2] = bv;
            }
        }
    }
    __syncthreads();

    // ---- pse + frame CE partial sum (mask all-true) ------------------------
    float lce = 0.f;
    for (int t = tid; t < TT; t += 256) {
        int cnt = 0;
        #pragma unroll
        for (int j = 0; j < NTR; j++) cnt += (t >= sbdy[j]) ? 1 : 0;
        int cid = s_tr[cnt];
        lce += g_lse[b * TT + t] - fr_logit[(size_t)(b * TT + t) * CC + cid];
    }
    #pragma unroll
    for (int o = 16; o > 0; o >>= 1) lce += __shfl_xor_sync(0xffffffffu, lce, o);
    if (lane == 0) sred[wrp] = lce;
    __syncthreads();
    if (tid == 0) {
        float s = 0.f;
        #pragma unroll
        for (int w = 0; w < 8; w++) s += sred[w];
        g_fr_part[b] = s;
    }
}

// ------------------- K6: GLC loss per (b, sorted-label k) ------------------
__global__ void k6_glc(const float* __restrict__ feat,
                       const int* __restrict__ transcript) {
    __shared__ int s_tr[LL];
    __shared__ int sb[NTR];
    __shared__ int s_m;
    __shared__ float sla[DD];
    __shared__ float s_sim[CC];
    __shared__ float sred[256];

    int b = blockIdx.x;
    int k = blockIdx.y;
    int tid = threadIdx.x;

    if (tid < LL) s_tr[tid] = transcript[b * LL + tid];
    if (tid < NTR) sb[tid] = g_bdy[b * NTR + tid];
    __syncthreads();

    if (tid < LL) {
        int v = s_tr[tid];
        int rank = 0;
        #pragma unroll
        for (int i = 0; i < LL; i++) rank += (s_tr[i] < v) ? 1 : 0;
        if (rank == k) s_m = tid;
    }
    __syncthreads();
    int m = s_m;
    int label = s_tr[m];
    int lo = (m == 0) ? 0 : sb[m - 1];
    int hi = (m == LL - 1) ? TT : sb[m];
    int cnt = hi - lo;

    float a0 = 0.f, a1 = 0.f;
    const float* fb = feat + ((size_t)b * (CC + TT) + CC) * DD;
    for (int t = lo; t < hi; t++) {
        a0 += fb[(size_t)t * DD + tid];
        a1 += fb[(size_t)t * DD + tid + 256];
    }
    float fc = (cnt > 0) ? (float)cnt : 1.f;
    a0 /= fc; a1 /= fc;

    sred[tid] = a0 * a0 + a1 * a1;
    __syncthreads();
    for (int s = 128; s > 0; s >>= 1) {
        if (tid < s) sred[tid] += sred[tid + s];
        __syncthreads();
    }
    float nrm = fmaxf(sqrtf(sred[0]), 1e-12f);
    sla[tid] = a0 / nrm;
    sla[tid + 256] = a1 / nrm;
    __syncthreads();

    int w = tid >> 5, lane = tid & 31;
    const float* tokb = feat + (size_t)b * (CC + TT) * DD;
    for (int jj = 0; jj < 6; jj++) {
        int j = w * 6 + jj;
        if (j < CC) {
            const float* tkr = tokb + (size_t)j * DD;
            float dot = 0.f, n2 = 0.f;
            for (int d = lane; d < DD; d += 32) {
                float tv = tkr[d];
                dot += sla[d] * tv;
                n2 += tv * tv;
            }
            #pragma unroll
            for (int o = 16; o > 0; o >>= 1) {
                dot += __shfl_xor_sync(0xffffffffu, dot, o);
                n2  += __shfl_xor_sync(0xffffffffu, n2, o);
            }
            if (lane == 0)
                s_sim[j] = dot / (fmaxf(sqrtf(n2), 1e-12f) * 0.1f);
        }
    }
    __syncthreads();

    if (tid == 0) {
        float mx = -INFINITY;
        for (int j = 0; j < CC; j++) mx = fmaxf(mx, s_sim[j]);
        float se = 0.f;
        for (int j = 0; j < CC; j++) se += __expf(s_sim[j] - mx);
        float lse = mx + __logf(se);
        g_glc_part[b * LL + k] = lse - s_sim[label];
    }
}

// ------------------- K7: tok BCE + final combine ---------------------------
__device__ __forceinline__ float log_sigmoid_f(float x) {
    return (x >= 0.f) ? -log1pf(__expf(-x)) : x - log1pf(__expf(x));
}

__global__ void k7_final(const float* __restrict__ tok_logit,
                         const float* __restrict__ y,
                         float* __restrict__ out) {
    __shared__ float sred[256];
    int tid = threadIdx.x;
    float v = 0.f;
    if (tid < BB * CC) {
        float x = tok_logit[tid];
        float yy = y[tid];
        v = -(yy * log_sigmoid_f(x) + (1.f - yy) * log_sigmoid_f(-x));
    }
    sred[tid] = v;
    __syncthreads();
    for (int s = 128; s > 0; s >>= 1) {
        if (tid < s) sred[tid] += sred[tid + s];
        __syncthreads();
    }
    if (tid == 0) {
        float tok = sred[0] / (float)(BB * CC);
        float frs = 0.f;
        for (int b = 0; b < BB; b++) frs += g_fr_part[b];
        float fr = frs / (float)(BB * TT);
        float gs = 0.f;
        for (int i = 0; i < BB * LL; i++) gs += g_glc_part[i];
        float glc = gs / (float)(BB * LL);
        out[0] = tok + fr + 0.1f * glc;
    }
}

// ------------------- launch -------------------------------------------------
extern "C" void kernel_launch(void* const* d_in, const int* in_sizes, int n_in,
                              void* d_out, int out_size) {
    const float* tok_logit  = (const float*)d_in[1];
    const float* fr_logit   = (const float*)d_in[2];
    const int*   transcript = (const int*)d_in[4];
    const float* vid        = (const float*)d_in[5];
    const float* feat       = (const float*)d_in[6];
    float* out = (float*)d_out;

    k1_softmax<<<(BB * TT) / 8, 256>>>(fr_logit);
    const int ntask = BB * 8 * TP8;
    k2_cross<<<(ntask + 7) / 8, 256>>>();
    k4_detect<<<BB, 256>>>(fr_logit, transcript);
    dim3 g6(BB, LL);
    k6_glc<<<g6, 256>>>(feat, transcript);
    k7_final<<<1, 256>>>(tok_logit, vid, out);
}

// round 5
// speedup vs baseline: 1.1025x; 1.1025x over previous
#include <cuda_runtime.h>
#include <math.h>

#define BB 4
#define TT 2048
#define CC 48
#define DD 512
#define LL 16
#define KK 9
#define CSZ 15
#define NTR 15
#define NCAND 45
#define WINLEN 19
#define TP8 (TT + 8)

// ------------------- device scratch (static, no allocs) -------------------
__device__ float g_prob[BB * TT * CC];
__device__ float g_lse[BB * TT];
__device__ float g_ent2[BB * TT];
__device__ float g_cross[BB * 8 * TP8];   // d = 1..8 (d=0 analytic)
__device__ float g_score[BB * TT];
__device__ int   g_bdy[BB * NTR];
__device__ float g_fr_part[BB];
__device__ float g_glc_part[BB * LL];

// order-preserving float -> uint32 (suppressed marker 0 is minimal)
__device__ __forceinline__ unsigned f2sortable(float f) {
    unsigned u = __float_as_uint(f);
    return (u & 0x80000000u) ? ~u : (u | 0x80000000u);
}

// pack a float literal into both halves of an f32x2 register
__device__ __forceinline__ unsigned long long pk2f(float c) {
    unsigned long long r;
    asm("mov.b64 %0, {%1,%1};" : "=l"(r) : "f"(c));
    return r;
}

// Cephes log2 on two values via packed f32x2 FMA pipe
__device__ __forceinline__ float2 fast_log2_x2(float x0, float x1) {
    unsigned u0 = __float_as_uint(x0), u1 = __float_as_uint(x1);
    int e0 = (int)(u0 >> 23) - 127, e1 = (int)(u1 >> 23) - 127;
    float m0 = __uint_as_float((u0 & 0x007fffffu) | 0x3f800000u);
    float m1 = __uint_as_float((u1 & 0x007fffffu) | 0x3f800000u);
    if (m0 > 1.4142135f) { m0 *= 0.5f; e0 += 1; }
    if (m1 > 1.4142135f) { m1 *= 0.5f; e1 += 1; }
    float z0 = m0 - 1.f, z1 = m1 - 1.f;
    unsigned long long Z, Z2, P, W, Y, E, R;
    asm("mov.b64 %0, {%1,%2};" : "=l"(Z) : "f"(z0), "f"(z1));
    asm("mul.rn.f32x2 %0, %1, %1;" : "=l"(Z2) : "l"(Z));
    P = pk2f(7.0376836292e-2f);
    asm("fma.rn.f32x2 %0, %1, %2, %3;" : "=l"(P) : "l"(P), "l"(Z), "l"(pk2f(-1.1514610310e-1f)));
    asm("fma.rn.f32x2 %0, %1, %2, %3;" : "=l"(P) : "l"(P), "l"(Z), "l"(pk2f( 1.1676998740e-1f)));
    asm("fma.rn.f32x2 %0, %1, %2, %3;" : "=l"(P) : "l"(P), "l"(Z), "l"(pk2f(-1.2420140846e-1f)));
    asm("fma.rn.f32x2 %0, %1, %2, %3;" : "=l"(P) : "l"(P), "l"(Z), "l"(pk2f( 1.4249322787e-1f)));
    asm("fma.rn.f32x2 %0, %1, %2, %3;" : "=l"(P) : "l"(P), "l"(Z), "l"(pk2f(-1.6668057665e-1f)));
    asm("fma.rn.f32x2 %0, %1, %2, %3;" : "=l"(P) : "l"(P), "l"(Z), "l"(pk2f( 2.0000714765e-1f)));
    asm("fma.rn.f32x2 %0, %1, %2, %3;" : "=l"(P) : "l"(P), "l"(Z), "l"(pk2f(-2.4999993993e-1f)));
    asm("fma.rn.f32x2 %0, %1, %2, %3;" : "=l"(P) : "l"(P), "l"(Z), "l"(pk2f( 3.3333331174e-1f)));
    asm("fma.rn.f32x2 %0, %1, %2, %3;" : "=l"(W) : "l"(Z2), "l"(pk2f(-0.5f)), "l"(Z));
    asm("mul.rn.f32x2 %0, %1, %2;" : "=l"(P) : "l"(P), "l"(Z));
    asm("fma.rn.f32x2 %0, %1, %2, %3;" : "=l"(Y) : "l"(P), "l"(Z2), "l"(W));
    float ef0 = (float)e0, ef1 = (float)e1;
    asm("mov.b64 %0, {%1,%2};" : "=l"(E) : "f"(ef0), "f"(ef1));
    asm("fma.rn.f32x2 %0, %1, %2, %3;" : "=l"(R) : "l"(Y), "l"(pk2f(1.44269504089f)), "l"(E));
    float r0, r1;
    asm("mov.b64 {%0,%1}, %2;" : "=f"(r0), "=f"(r1) : "l"(R));
    return make_float2(r0, r1);
}

// ------------------- K1: softmax rows + lse + ent2 ------------------------
__global__ void k1_softmax(const float* __restrict__ fr) {
    int gw = (blockIdx.x * blockDim.x + threadIdx.x) >> 5;
    int lane = threadIdx.x & 31;
    if (gw >= BB * TT) return;
    const float* row = fr + (size_t)gw * CC;
    float x0 = row[lane];
    float x1 = (lane < 16) ? row[lane + 32] : -INFINITY;
    float m = fmaxf(x0, x1);
    #pragma unroll
    for (int o = 16; o > 0; o >>= 1) m = fmaxf(m, __shfl_xor_sync(0xffffffffu, m, o));
    float e0 = __expf(x0 - m);
    float e1 = (lane < 16) ? __expf(x1 - m) : 0.f;
    float s = e0 + e1;
    #pragma unroll
    for (int o = 16; o > 0; o >>= 1) s += __shfl_xor_sync(0xffffffffu, s, o);
    float inv = 1.f / s;
    float p0 = e0 * inv, p1 = e1 * inv;
    float ent = (p0 > 0.f) ? p0 * __log2f(p0) : 0.f;
    if (lane < 16) ent += (p1 > 0.f) ? p1 * __log2f(p1) : 0.f;
    #pragma unroll
    for (int o = 16; o > 0; o >>= 1) ent += __shfl_xor_sync(0xffffffffu, ent, o);
    float* pr = g_prob + (size_t)gw * CC;
    pr[lane] = p0;
    if (lane < 16) pr[lane + 32] = p1;
    if (lane == 0) {
        g_lse[gw] = m + __logf(s);
        g_ent2[gw] = ent;
    }
}

// ------------------- K2: crossD[d][rmin], d = 1..8, dual-pipe log ----------
__global__ void k2_cross() {
    int gw = (blockIdx.x * blockDim.x + threadIdx.x) >> 5;
    int lane = threadIdx.x & 31;
    const int ntask = BB * 8 * TP8;
    if (gw >= ntask) return;
    int b = gw / (8 * TP8);
    int rem = gw % (8 * TP8);
    int d = rem / TP8 + 1;   // 1..8 (warp-uniform)
    int r4 = rem % TP8;
    int r1 = r4 - 4;
    int r2 = r1 + d;
    const float2* base = (const float2*)(g_prob + (size_t)b * TT * CC);
    float acc = 0.f;
    if (lane < 24) {
        float2 a = (r1 >= 0 && r1 < TT) ? base[r1 * 24 + lane] : make_float2(0.f, 0.f);
        float2 c = (r2 >= 0 && r2 < TT) ? base[r2 * 24 + lane] : make_float2(0.f, 0.f);
        float sv0 = a.x + c.x, sv1 = a.y + c.y;
        float x0 = 0.5f * sv0 + 1e-32f;
        float x1 = 0.5f * sv1 + 1e-32f;
        float lg0, lg1;
        if (d <= 3) {              // FMA-pipe poly warps
            float2 lg = fast_log2_x2(x0, x1);
            lg0 = lg.x; lg1 = lg.y;
        } else {                   // MUFU warps
            lg0 = __log2f(x0);
            lg1 = __log2f(x1);
        }
        acc = sv0 * lg0 + sv1 * lg1;
    }
    #pragma unroll
    for (int o = 16; o > 0; o >>= 1) acc += __shfl_xor_sync(0xffffffffu, acc, o);
    if (lane == 0) g_cross[(b * 8 + (d - 1)) * TP8 + r4] = acc;
}

// ------------------- K3: boundary score per (b,t) (reduced form) -----------
__global__ void k3_score() {
    int idx = blockIdx.x * blockDim.x + threadIdx.x;
    if (idx >= BB * TT) return;
    int b = idx / TT;
    int t = idx % TT;
    float se = 0.f;
    #pragma unroll
    for (int i = 0; i < 4; i++) {
        int r = t - 4 + i;
        se += (r >= 0) ? g_ent2[b * TT + r] : 0.f;
    }
    float cs = 0.f;
    #pragma unroll
    for (int d = 1; d <= 8; d++) {
        const float* crb = g_cross + (size_t)(b * 8 + d - 1) * TP8 + t;
        #pragma unroll
        for (int i = 0; i + d <= 8; i++) {
            float w = ((i < 4) == ((i + d) < 4)) ? 2.f : -2.f;
            cs += w * crb[i];
        }
    }
    float sc = (4.f * se + cs) * (1.f / 81.f);
    if (t == 0) sc = -INFINITY;
    g_score[idx] = sc;
}

// ------------------- K4: detect + CE, per batch ----------------------------
__global__ void k4_detect(const float* __restrict__ fr_logit,
                          const int* __restrict__ transcript) {
    __shared__ __align__(16) unsigned ss[TT];   // sortable scores (0 = suppressed)
    __shared__ float sfs[TT];                   // float scores
    __shared__ int scand[NCAND];
    __shared__ int scand2[NCAND];
    __shared__ int s_tr[LL];
    __shared__ float scls[NTR * NCAND];
    __shared__ signed char sdir[NCAND * 31];
    __shared__ int sbdy[NTR];
    __shared__ float sred[8];

    int b = blockIdx.x;
    int tid = threadIdx.x;
    int lane = tid & 31;
    int wrp = tid >> 5;

    for (int t = tid; t < TT; t += 256) {
        float sc = g_score[b * TT + t];
        sfs[t] = sc;
        ss[t] = f2sortable(sc);
    }
    if (tid < LL) s_tr[tid] = transcript[b * LL + tid];
    __syncthreads();

    // ---- warp 0: 45 incremental argmax iterations --------------------------
    if (tid < 32) {
        const uint4* s4c = (const uint4*)ss;
        unsigned v0 = 0u, v1 = 0u;
        #pragma unroll
        for (int q = 0; q < 8; q++) {
            uint4 a = s4c[lane * 8 + q];
            uint4 c = s4c[(lane + 32) * 8 + q];
            v0 = max(v0, max(max(a.x, a.y), max(a.z, a.w)));
            v1 = max(v1, max(max(c.x, c.y), max(c.z, c.w)));
        }
        for (int it = 0; it < NCAND; it++) {
            unsigned loc = max(v0, v1);
            unsigned mv = __reduce_max_sync(0xffffffffu, loc);
            unsigned m0 = __ballot_sync(0xffffffffu, v0 == mv);
            unsigned m1 = __ballot_sync(0xffffffffu, v1 == mv);
            int seg = m0 ? (__ffs(m0) - 1) : (32 + __ffs(m1) - 1);
            unsigned val = ss[seg * 32 + lane];
            unsigned mask = __ballot_sync(0xffffffffu, val == mv);
            int pick = seg * 32 + (__ffs(mask) - 1);
            if (lane == 0) scand[it] = pick;
            __syncwarp();
            // suppression + rescan fused: <=3 lanes, uint4 granularity
            int lo = pick - WINLEN, hi = pick + WINLEN;
            int slo = (lo < 0 ? 0 : lo) >> 5;
            int shi = ((hi > TT - 1 ? TT - 1 : hi)) >> 5;
            int nseg = shi - slo + 1;
            unsigned nv = 0u;
            if (lane < nseg) {
                int s = slo + lane;
                uint4* s4 = (uint4*)(ss + s * 32);
                int base = s * 32;
                #pragma unroll
                for (int q = 0; q < 8; q++) {
                    uint4 v = s4[q];
                    int idx = base + q * 4;
                    v.x = (idx     >= lo && idx     <= hi) ? 0u : v.x;
                    v.y = (idx + 1 >= lo && idx + 1 <= hi) ? 0u : v.y;
                    v.z = (idx + 2 >= lo && idx + 2 <= hi) ? 0u : v.z;
                    v.w = (idx + 3 >= lo && idx + 3 <= hi) ? 0u : v.w;
                    s4[q] = v;
                    nv = max(nv, max(max(v.x, v.y), max(v.z, v.w)));
                }
            }
            #pragma unroll
            for (int k2 = 0; k2 < 3; k2++) {
                unsigned m = __shfl_sync(0xffffffffu, nv, k2);
                int sg = slo + k2;
                if (k2 < nseg) {
                    if (sg == lane) v0 = m;
                    if (sg == lane + 32) v1 = m;
                }
            }
            __syncwarp();
        }
        // parallel rank sort (distinct indices -> unique ranks)
        int c0 = scand[lane];
        int c1 = (lane + 32 < NCAND) ? scand[lane + 32] : 0x7fffffff;
        int r0 = 0, r1 = 0;
        for (int j = 0; j < NCAND; j++) {
            int cj = scand[j];
            r0 += (cj < c0);
            r1 += (cj < c1);
        }
        scand2[r0] = c0;
        if (lane + 32 < NCAND) scand2[r1] = c1;
    }
    __syncthreads();

    // ---- cls matrix --------------------------------------------------------
    const float* pb = g_prob + (size_t)b * TT * CC;
    for (int e = tid; e < NTR * NCAND; e += 256) {
        int tr_i = e / NCAND;
        int n = e % NCAND;
        int cn = scand2[n];
        int ca = s_tr[tr_i], cb = s_tr[tr_i + 1];
        float sacc = 0.f;
        #pragma unroll
        for (int sft = 0; sft < CSZ; sft++) {
            int r = cn + sft - 7;
            if (r >= 0 && r < TT) {
                float sign = (sft < 7) ? 1.f : -1.f;
                sacc += sign * (pb[r * CC + ca] - pb[r * CC + cb]);
            }
        }
        scls[e] = sacc * (1.f / 30.f) + sfs[cn];
    }
    __syncthreads();

    // ---- DP: 31 lanes, one column each; backtrace on lane 0 ----------------
    if (tid < 32) {
        int j = lane;
        const float FINF = INFINITY;
        bool active = (j < 31);
        float prev;
        if (j == 0) prev = 0.f;
        else if (j == 1) prev = -scls[0 * NCAND + 0];
        else prev = FINF;
        if (active) sdir[j] = (j == 1) ? 1 : 0;
        int ta = j >> 1; if (ta > NTR - 1) ta = NTR - 1;
        bool even = ((j & 1) == 0);
        for (int ii = 1; ii < NCAND; ii++) {
            float dm1 = __shfl_up_sync(0xffffffffu, prev, 1);
            float dm2 = __shfl_up_sync(0xffffffffu, prev, 2);
            if (j < 1) dm1 = FINF;
            if (j < 2) dm2 = FINF;
            float nv; signed char nd;
            if (j >= 2) {
                if (even) {
                    nv = fminf(prev, dm1);
                    nd = (prev < dm1) ? 0 : 1;
                } else {
                    nv = -scls[ta * NCAND + ii] + fminf(dm1, dm2);
                    nd = (dm1 < dm2) ? 1 : 2;
                }
            } else if (j == 0) {
                nv = (ii < NCAND - NTR) ? 0.f : FINF; nd = 0;
            } else {
                bool ok = (ii <= NCAND - NTR);
                nv = ok ? -scls[0 * NCAND + ii] : FINF;
                nd = ok ? 1 : 0;
            }
            prev = nv;
            if (active) sdir[ii * 31 + j] = nd;
        }
        float p30 = __shfl_sync(0xffffffffu, prev, 30);
        float p29 = __shfl_sync(0xffffffffu, prev, 29);
        if (j == 0) {
            int cj = (p30 < p29) ? 30 : 29;
            int outi[NCAND];
            #pragma unroll
            for (int ii = NCAND - 1; ii >= 0; ii--) {
                outi[ii] = (cj & 1) ? (cj >> 1) : NTR;
                cj -= sdir[ii * 31 + cj];
            }
            int res[NTR];
            #pragma unroll
            for (int k2 = 0; k2 < NTR; k2++) res[k2] = 0;
            #pragma unroll
            for (int ii = 0; ii < NCAND; ii++) {
                int oi = outi[ii];
                if (oi < NTR) res[oi] = ii;
            }
            #pragma unroll
            for (int k2 = 0; k2 < NTR; k2++) {
                int bv = scand2[res[k2]];
                sbdy[k2] = bv;
                g_bdy[b * NTR + k2] = bv;
            }
        }
    }
    __syncthreads();

    // ---- pse + frame CE partial sum (mask all-true) ------------------------
    float lce = 0.f;
    for (int t = tid; t < TT; t += 256) {
        int cnt = 0;
        #pragma unroll
        for (int j = 0; j < NTR; j++) cnt += (t >= sbdy[j]) ? 1 : 0;
        int cid = s_tr[cnt];
        lce += g_lse[b * TT + t] - fr_logit[(size_t)(b * TT + t) * CC + cid];
    }
    #pragma unroll
    for (int o = 16; o > 0; o >>= 1) lce += __shfl_xor_sync(0xffffffffu, lce, o);
    if (lane == 0) sred[wrp] = lce;
    __syncthreads();
    if (tid == 0) {
        float s = 0.f;
        #pragma unroll
        for (int w = 0; w < 8; w++) s += sred[w];
        g_fr_part[b] = s;
    }
}

// ------------------- K6: GLC loss per (b, sorted-label k) ------------------
__global__ void k6_glc(const float* __restrict__ feat,
                       const int* __restrict__ transcript) {
    __shared__ int s_tr[LL];
    __shared__ int sb[NTR];
    __shared__ int s_m;
    __shared__ float4 sla4[DD / 4];     // normalized label-mean feature
    __shared__ float4 stmp[DD / 4];
    __shared__ float s_sim[CC];
    __shared__ float sred[256];
    __shared__ float snrm;

    int b = blockIdx.x;
    int k = blockIdx.y;
    int tid = threadIdx.x;

    if (tid < LL) s_tr[tid] = transcript[b * LL + tid];
    if (tid < NTR) sb[tid] = g_bdy[b * NTR + tid];
    __syncthreads();

    if (tid < LL) {
        int v = s_tr[tid];
        int rank = 0;
        #pragma unroll
        for (int i = 0; i < LL; i++) rank += (s_tr[i] < v) ? 1 : 0;
        if (rank == k) s_m = tid;
    }
    __syncthreads();
    int m = s_m;
    int label = s_tr[m];
    int lo = (m == 0) ? 0 : sb[m - 1];
    int hi = (m == LL - 1) ? TT : sb[m];
    int cnt = hi - lo;

    // ---- label-mean over rows [lo, hi): float4, 2 rows in flight, unroll 4 --
    int q = tid & 127;       // float4 slot within a row
    int half = tid >> 7;     // row parity
    const float4* fb4 = (const float4*)(feat + ((size_t)b * (CC + TT) + CC) * DD);
    float4 a0 = make_float4(0.f, 0.f, 0.f, 0.f);
    float4 a1 = a0, a2 = a0, a3 = a0;
    int t = lo + half;
    for (; t + 6 < hi; t += 8) {
        float4 x0 = fb4[(size_t)t * 128 + q];
        float4 x1 = fb4[(size_t)(t + 2) * 128 + q];
        float4 x2 = fb4[(size_t)(t + 4) * 128 + q];
        float4 x3 = fb4[(size_t)(t + 6) * 128 + q];
        a0.x += x0.x; a0.y += x0.y; a0.z += x0.z; a0.w += x0.w;
        a1.x += x1.x; a1.y += x1.y; a1.z += x1.z; a1.w += x1.w;
        a2.x += x2.x; a2.y += x2.y; a2.z += x2.z; a2.w += x2.w;
        a3.x += x3.x; a3.y += x3.y; a3.z += x3.z; a3.w += x3.w;
    }
    for (; t < hi; t += 2) {
        float4 x0 = fb4[(size_t)t * 128 + q];
        a0.x += x0.x; a0.y += x0.y; a0.z += x0.z; a0.w += x0.w;
    }
    a0.x += a1.x + a2.x + a3.x;
    a0.y += a1.y + a2.y + a3.y;
    a0.z += a1.z + a2.z + a3.z;
    a0.w += a1.w + a2.w + a3.w;
    if (half == 1) stmp[q] = a0;
    __syncthreads();
    float sq = 0.f;
    float4 mm = make_float4(0.f, 0.f, 0.f, 0.f);
    if (half == 0) {
        float4 o = stmp[q];
        float fc = (cnt > 0) ? (float)cnt : 1.f;
        float inv = 1.f / fc;
        mm.x = (a0.x + o.x) * inv;
        mm.y = (a0.y + o.y) * inv;
        mm.z = (a0.z + o.z) * inv;
        mm.w = (a0.w + o.w) * inv;
        sq = mm.x * mm.x + mm.y * mm.y + mm.z * mm.z + mm.w * mm.w;
    }
    sred[tid] = sq;
    __syncthreads();
    for (int s = 128; s > 0; s >>= 1) {
        if (tid < s) sred[tid] += sred[tid + s];
        __syncthreads();
    }
    if (tid == 0) snrm = 1.f / fmaxf(sqrtf(sred[0]), 1e-12f);
    __syncthreads();
    if (half == 0) {
        float inm = snrm;
        sla4[q] = make_float4(mm.x * inm, mm.y * inm, mm.z * inm, mm.w * inm);
    }
    __syncthreads();

    // ---- cosine sims vs 48 token rows: float4, 8 warps x 6 rows -------------
    int w = tid >> 5, lane = tid & 31;
    const float4* tokb4 = (const float4*)(feat + (size_t)b * (CC + TT) * DD);
    #pragma unroll
    for (int jj = 0; jj < 6; jj++) {
        int j = w * 6 + jj;
        const float4* tkr = tokb4 + (size_t)j * 128;
        float dot = 0.f, n2 = 0.f;
        #pragma unroll
        for (int kk = 0; kk < 4; kk++) {
            int idx = lane + 32 * kk;
            float4 tv = tkr[idx];
            float4 lv = sla4[idx];
            dot += lv.x * tv.x + lv.y * tv.y + lv.z * tv.z + lv.w * tv.w;
            n2  += tv.x * tv.x + tv.y * tv.y + tv.z * tv.z + tv.w * tv.w;
        }
        #pragma unroll
        for (int o = 16; o > 0; o >>= 1) {
            dot += __shfl_xor_sync(0xffffffffu, dot, o);
            n2  += __shfl_xor_sync(0xffffffffu, n2, o);
        }
        if (lane == 0)
            s_sim[j] = dot / (fmaxf(sqrtf(n2), 1e-12f) * 0.1f);
    }
    __syncthreads();

    if (tid == 0) {
        float mx = -INFINITY;
        for (int j = 0; j < CC; j++) mx = fmaxf(mx, s_sim[j]);
        float se = 0.f;
        for (int j = 0; j < CC; j++) se += __expf(s_sim[j] - mx);
        float lse = mx + __logf(se);
        g_glc_part[b * LL + k] = lse - s_sim[label];
    }
}

// ------------------- K7: tok BCE + final combine ---------------------------
__device__ __forceinline__ float log_sigmoid_f(float x) {
    return (x >= 0.f) ? -log1pf(__expf(-x)) : x - log1pf(__expf(x));
}

__global__ void k7_final(const float* __restrict__ tok_logit,
                         const float* __restrict__ y,
                         float* __restrict__ out) {
    __shared__ float sred[256];
    int tid = threadIdx.x;
    float v = 0.f;
    if (tid < BB * CC) {
        float x = tok_logit[tid];
        float yy = y[tid];
        v = -(yy * log_sigmoid_f(x) + (1.f - yy) * log_sigmoid_f(-x));
    }
    sred[tid] = v;
    __syncthreads();
    for (int s = 128; s > 0; s >>= 1) {
        if (tid < s) sred[tid] += sred[tid + s];
        __syncthreads();
    }
    if (tid == 0) {
        float tok = sred[0] / (float)(BB * CC);
        float frs = 0.f;
        for (int b = 0; b < BB; b++) frs += g_fr_part[b];
        float fr = frs / (float)(BB * TT);
        float gs = 0.f;
        for (int i = 0; i < BB * LL; i++) gs += g_glc_part[i];
        float glc = gs / (float)(BB * LL);
        out[0] = tok + fr + 0.1f * glc;
    }
}

// ------------------- launch -------------------------------------------------
extern "C" void kernel_launch(void* const* d_in, const int* in_sizes, int n_in,
                              void* d_out, int out_size) {
    const float* tok_logit  = (const float*)d_in[1];
    const float* fr_logit   = (const float*)d_in[2];
    const int*   transcript = (const int*)d_in[4];
    const float* vid        = (const float*)d_in[5];
    const float* feat       = (const float*)d_in[6];
    float* out = (float*)d_out;

    k1_softmax<<<(BB * TT) / 8, 256>>>(fr_logit);
    const int ntask = BB * 8 * TP8;
    k2_cross<<<(ntask + 7) / 8, 256>>>();
    k3_score<<<(BB * TT + 255) / 256, 256>>>();
    k4_detect<<<BB, 256>>>(fr_logit, transcript);
    dim3 g6(BB, LL);
    k6_glc<<<g6, 256>>>(feat, transcript);
    k7_final<<<1, 256>>>(tok_logit, vid, out);
}